// round 9
// baseline (speedup 1.0000x reference)
#include <cuda_runtime.h>
#include <cuda_bf16.h>
#include <cstdint>

#define NTOK 64
#define DIM  192
#define NH   6
#define HD   32
#define NWIN 2048
#define MTOT (NWIN * NTOK)     // 131072
#define QKVN 576

// ------------------------- device scratch (static) -------------------------
__device__ float g_qkv[MTOT * QKVN];            // qkv output, fp32
__device__ float g_att[MTOT * DIM];             // attention output, fp32
__device__ __nv_bfloat16 g_wqh[QKVN * DIM];     // w_qkv^T hi (scaled q cols)
__device__ __nv_bfloat16 g_wql[QKVN * DIM];     // w_qkv^T lo
__device__ __nv_bfloat16 g_wph[DIM * DIM];      // w_proj^T hi
__device__ __nv_bfloat16 g_wpl[DIM * DIM];      // w_proj^T lo
__device__ float g_bq[QKVN];                    // qkv bias (scaled q part)

__device__ __forceinline__ uint32_t smem_u32(const void* p) {
    uint32_t a;
    asm("{ .reg .u64 t; cvta.to.shared.u64 t, %1; cvt.u32.u64 %0, t; }"
        : "=r"(a) : "l"(p));
    return a;
}
__device__ __forceinline__ uint32_t pkbf(__nv_bfloat16 a, __nv_bfloat16 b) {
    return (uint32_t)__bfloat16_as_ushort(a)
         | ((uint32_t)__bfloat16_as_ushort(b) << 16);
}
__device__ __forceinline__ float ex2(float x) {
    float y; asm("ex2.approx.ftz.f32 %0, %1;" : "=f"(y) : "f"(x)); return y;
}
// split a,b into bf16 hi (packed) and lo (packed residual)
__device__ __forceinline__ void split2(float a, float b, uint32_t& hi, uint32_t& lo) {
    __nv_bfloat16 ha = __float2bfloat16(a);
    __nv_bfloat16 hb = __float2bfloat16(b);
    hi = pkbf(ha, hb);
    lo = pkbf(__float2bfloat16(a - __bfloat162float(ha)),
              __float2bfloat16(b - __bfloat162float(hb)));
}

#define LDSM4(r, addr)                                                      \
    asm volatile("ldmatrix.sync.aligned.m8n8.x4.shared.b16 "                \
                 "{%0,%1,%2,%3}, [%4];"                                     \
                 : "=r"((r)[0]), "=r"((r)[1]), "=r"((r)[2]), "=r"((r)[3])   \
                 : "r"(addr))

#define MMA16816(c, a, b0, b1)                                              \
    asm volatile("mma.sync.aligned.m16n8k16.row.col.f32.bf16.bf16.f32 "     \
                 "{%0,%1,%2,%3}, {%4,%5,%6,%7}, {%8,%9}, {%0,%1,%2,%3};"    \
                 : "+f"((c)[0]), "+f"((c)[1]), "+f"((c)[2]), "+f"((c)[3])   \
                 : "r"((a)[0]), "r"((a)[1]), "r"((a)[2]), "r"((a)[3]),      \
                   "r"(b0), "r"(b1))

// ------------------------- prep: split + transpose weights -------------------------
__global__ void prep_kernel(const float* __restrict__ wqkv,
                            const float* __restrict__ bqkv,
                            const float* __restrict__ wproj)
{
    const float SCALE = 0.17677669529663689f;
    int i = blockIdx.x * 256 + threadIdx.x;
    if (i < QKVN * DIM) {
        int n = i % QKVN, k = i / QKVN;
        float v = wqkv[k * QKVN + n];
        if (n < DIM) v *= SCALE;
        __nv_bfloat16 h = __float2bfloat16(v);
        g_wqh[n * DIM + k] = h;
        g_wql[n * DIM + k] = __float2bfloat16(v - __bfloat162float(h));
    }
    if (i < DIM * DIM) {
        int n = i % DIM, k = i / DIM;
        float v = wproj[k * DIM + n];
        __nv_bfloat16 h = __float2bfloat16(v);
        g_wph[n * DIM + k] = h;
        g_wpl[n * DIM + k] = __float2bfloat16(v - __bfloat162float(h));
    }
    if (i < QKVN) g_bq[i] = (i < DIM) ? bqkv[i] * SCALE : bqkv[i];
}

// --------- mma.sync bf16-split GEMM (unchanged, proven) ----------
#define MT   128
#define KD   192
#define ASTR 200
#define BSTR 200
#define CSTR 68
#define OFF_AH 0
#define OFF_AL (MT * ASTR * 2)
#define OFF_B  (2 * MT * ASTR * 2)
#define OFF_BH OFF_B
#define OFF_BL (OFF_B + 64 * BSTR * 2)
#define OFF_C  OFF_B
#define GSMEM  (OFF_B + 2 * 64 * BSTR * 2)

__global__ __launch_bounds__(256, 1)
void gemm_mma(const float* __restrict__ A,
              const __nv_bfloat16* __restrict__ Bh,
              const __nv_bfloat16* __restrict__ Bl,
              const float* __restrict__ bias,
              float* __restrict__ C,
              int ldc, int ntot)
{
    extern __shared__ char smem[];
    __nv_bfloat16* sAh = (__nv_bfloat16*)(smem + OFF_AH);
    __nv_bfloat16* sAl = (__nv_bfloat16*)(smem + OFF_AL);
    float*         sC  = (float*)(smem + OFF_C);
    const uint32_t sb  = smem_u32(smem);

    const int tid  = threadIdx.x;
    const int wid  = tid >> 5;
    const int lane = tid & 31;
    const int wm   = wid >> 1;
    const int wn   = wid & 1;

    {
        const float* ag = A + (size_t)blockIdx.x * MT * KD;
        #pragma unroll
        for (int q = 0; q < 24; ++q) {
            int f  = tid + q * 256;
            int r  = f / 48, c4 = (f % 48) * 4;
            float4 v = *(const float4*)&ag[(size_t)r * KD + c4];
            uint2 hp, lp;
            split2(v.x, v.y, hp.x, lp.x);
            split2(v.z, v.w, hp.y, lp.y);
            *(uint2*)&sAh[r * ASTR + c4] = hp;
            *(uint2*)&sAl[r * ASTR + c4] = lp;
        }
    }

    const int asub = lane >> 3, ar = lane & 7;
    uint32_t aeo[2], beo[2];
    #pragma unroll
    for (int t = 0; t < 2; ++t) {
        int row = wm * 32 + t * 16 + ar + (asub & 1) * 8;
        int col = (asub >> 1) * 8;
        aeo[t] = (uint32_t)(row * ASTR + col) * 2u;
    }
    #pragma unroll
    for (int p = 0; p < 2; ++p) {
        int row = wn * 32 + p * 16 + ar + (asub >> 1) * 8;
        int col = (asub & 1) * 8;
        beo[p] = (uint32_t)(row * BSTR + col) * 2u;
    }

    const int nchunks = ntot / 64;
    #pragma unroll 1
    for (int nc = 0; nc < nchunks; ++nc) {
        __syncthreads();

        #pragma unroll
        for (int s2 = 0; s2 < 2; ++s2) {
            const __nv_bfloat16* src = (s2 ? Bl : Bh) + (size_t)(nc * 64) * KD;
            __nv_bfloat16* dst = (__nv_bfloat16*)(smem + (s2 ? OFF_BL : OFF_BH));
            #pragma unroll
            for (int q = 0; q < 6; ++q) {
                int g = tid + q * 256;
                int row = g / 24, gg = g % 24;
                *(uint4*)&dst[row * BSTR + gg * 8] =
                    *(const uint4*)&src[(size_t)row * KD + gg * 8];
            }
        }
        __syncthreads();

        float c[2][4][4];
        #pragma unroll
        for (int t = 0; t < 2; ++t)
            #pragma unroll
            for (int f = 0; f < 4; ++f)
                #pragma unroll
                for (int j = 0; j < 4; ++j) c[t][f][j] = 0.f;

        #pragma unroll 1
        for (int s = 0; s < 3; ++s) {
            uint32_t ab = sb + (s == 2 ? OFF_AL : OFF_AH);
            uint32_t bb = sb + (s == 1 ? OFF_BL : OFF_BH);
            #pragma unroll
            for (int k16 = 0; k16 < 12; ++k16) {
                uint32_t ko = (uint32_t)k16 * 32u;
                uint32_t a[2][4], bf[2][4];
                LDSM4(a[0], ab + aeo[0] + ko);
                LDSM4(a[1], ab + aeo[1] + ko);
                LDSM4(bf[0], bb + beo[0] + ko);
                LDSM4(bf[1], bb + beo[1] + ko);
                #pragma unroll
                for (int t = 0; t < 2; ++t) {
                    MMA16816(c[t][0], a[t], bf[0][0], bf[0][1]);
                    MMA16816(c[t][1], a[t], bf[0][2], bf[0][3]);
                    MMA16816(c[t][2], a[t], bf[1][0], bf[1][1]);
                    MMA16816(c[t][3], a[t], bf[1][2], bf[1][3]);
                }
            }
        }
        __syncthreads();

        #pragma unroll
        for (int t = 0; t < 2; ++t) {
            int r0 = wm * 32 + t * 16 + (lane >> 2);
            #pragma unroll
            for (int f = 0; f < 4; ++f) {
                int cc = wn * 32 + f * 8 + (lane & 3) * 2;
                sC[r0 * CSTR + cc]           = c[t][f][0];
                sC[r0 * CSTR + cc + 1]       = c[t][f][1];
                sC[(r0 + 8) * CSTR + cc]     = c[t][f][2];
                sC[(r0 + 8) * CSTR + cc + 1] = c[t][f][3];
            }
        }
        __syncthreads();

        const int n0 = nc * 64;
        float* crow = C + (size_t)blockIdx.x * MT * ldc + n0;
        #pragma unroll
        for (int q = 0; q < 8; ++q) {
            int f = tid + q * 256;
            int r = f >> 4, c4 = (f & 15) * 4;
            float4 v = *(float4*)&sC[r * CSTR + c4];
            v.x += __ldg(&bias[n0 + c4 + 0]);
            v.y += __ldg(&bias[n0 + c4 + 1]);
            v.z += __ldg(&bias[n0 + c4 + 2]);
            v.w += __ldg(&bias[n0 + c4 + 3]);
            *(float4*)&crow[(size_t)r * ldc + c4] = v;
        }
    }
}

// -------- FA-style tensor-core attention: CTA per (window, head) --------
// SMEM bf16 tiles: Q,K 64x32 (stride 40), V^T 32x64 (stride 72), hi/lo each.
#define QST 40
#define VST 72
#define OFQH 0
#define OFQL (OFQH + 64 * QST * 2)     // 5120
#define OFKH (OFQL + 64 * QST * 2)     // 10240
#define OFKL (OFKH + 64 * QST * 2)     // 15360
#define OFVH (OFKL + 64 * QST * 2)     // 20480
#define OFVL (OFVH + 32 * VST * 2)     // 25088
#define OFMSK (OFVL + 32 * VST * 2)    // 29696
#define OFRP  (OFMSK + 64 * 65 * 4)    // 46336
#define ATT_SMEM (OFRP + 240 * 4)      // 47296

__global__ __launch_bounds__(128, 4)
void attn_mma(const float* __restrict__ mask,
              const float* __restrict__ rpbt)
{
    extern __shared__ char smem[];
    const uint32_t sb = smem_u32(smem);
    float* smask = (float*)(smem + OFMSK);
    float* srp   = (float*)(smem + OFRP);

    const int tid  = threadIdx.x;
    const int wid  = tid >> 5;
    const int lane = tid & 31;
    const int win  = blockIdx.x;
    const int head = blockIdx.y;
    const float LOG2E = 1.4426950408889634f;

    const float* base = g_qkv + (size_t)win * (NTOK * QKVN) + head * HD;

    // ---- stage Q, K (split bf16, row-major stride 40) ----
    #pragma unroll
    for (int q = 0; q < 4; ++q) {
        int f = tid + q * 128;                 // 512 float4
        int r = f >> 3, c4 = (f & 7) * 4;
        const float* src = base + (size_t)r * QKVN + c4;
        float4 vq = *(const float4*)src;
        float4 vk = *(const float4*)(src + 192);
        uint2 h, l;
        split2(vq.x, vq.y, h.x, l.x); split2(vq.z, vq.w, h.y, l.y);
        *(uint2*)(smem + OFQH + (r * QST + c4) * 2) = h;
        *(uint2*)(smem + OFQL + (r * QST + c4) * 2) = l;
        split2(vk.x, vk.y, h.x, l.x); split2(vk.z, vk.w, h.y, l.y);
        *(uint2*)(smem + OFKH + (r * QST + c4) * 2) = h;
        *(uint2*)(smem + OFKL + (r * QST + c4) * 2) = l;
    }
    // ---- stage V transposed (32 x 64, stride 72) ----
    #pragma unroll
    for (int q = 0; q < 4; ++q) {
        int f = tid + q * 128;
        int r = f >> 3, c4 = (f & 7) * 4;
        float4 v = *(const float4*)(base + (size_t)r * QKVN + 384 + c4);
        #pragma unroll
        for (int i = 0; i < 4; ++i) {
            float x = (i == 0) ? v.x : (i == 1) ? v.y : (i == 2) ? v.z : v.w;
            __nv_bfloat16 h = __float2bfloat16(x);
            *(__nv_bfloat16*)(smem + OFVH + ((c4 + i) * VST + r) * 2) = h;
            *(__nv_bfloat16*)(smem + OFVL + ((c4 + i) * VST + r) * 2) =
                __float2bfloat16(x - __bfloat162float(h));
        }
    }
    // ---- stage mask (fp32, stride 65) + rpbt column ----
    {
        const float* mg = mask + (size_t)(win & 63) * (NTOK * NTOK);
        #pragma unroll
        for (int q = 0; q < 8; ++q) {
            int f = tid + q * 128;             // 1024 float4
            int r = f >> 4, c = (f & 15) * 4;
            float4 v = *(const float4*)&mg[r * 64 + c];
            smask[r * 65 + c + 0] = v.x; smask[r * 65 + c + 1] = v.y;
            smask[r * 65 + c + 2] = v.z; smask[r * 65 + c + 3] = v.w;
        }
        #pragma unroll
        for (int q = 0; q < 2; ++q) {
            int f = tid + q * 128;
            if (f < 225) srp[f] = __ldg(&rpbt[f * NH + head]);
        }
    }
    __syncthreads();

    // ---- per-warp fragment offsets (clone of gemm conventions) ----
    const int asub = lane >> 3, ar = lane & 7;
    const uint32_t aqoff =
        (uint32_t)((wid * 16 + ar + (asub & 1) * 8) * QST + (asub >> 1) * 8) * 2u;
    const uint32_t koff =
        (uint32_t)((ar + (asub >> 1) * 8) * QST + (asub & 1) * 8) * 2u;
    const uint32_t voff =
        (uint32_t)((ar + (asub >> 1) * 8) * VST + (asub & 1) * 8) * 2u;

    // ---- S = Q @ K^T (3-pass split), S tile 16x64 per warp ----
    float s[4][2][4];
    #pragma unroll
    for (int j = 0; j < 4; ++j)
        #pragma unroll
        for (int h = 0; h < 2; ++h)
            #pragma unroll
            for (int e = 0; e < 4; ++e) s[j][h][e] = 0.f;

    #pragma unroll
    for (int pass = 0; pass < 3; ++pass) {
        uint32_t ab = sb + (pass == 2 ? OFQL : OFQH);
        uint32_t bb = sb + (pass == 1 ? OFKL : OFKH);
        #pragma unroll
        for (int ks = 0; ks < 2; ++ks) {
            uint32_t aq[4];
            LDSM4(aq, ab + aqoff + ks * 32);
            #pragma unroll
            for (int j16 = 0; j16 < 4; ++j16) {
                uint32_t bk[4];
                LDSM4(bk, bb + koff + j16 * (16 * QST * 2) + ks * 32);
                MMA16816(s[j16][0], aq, bk[0], bk[1]);
                MMA16816(s[j16][1], aq, bk[2], bk[3]);
            }
        }
    }

    // ---- bias + mask on fragments ----
    const int g  = wid * 16 + (lane >> 2);
    const int n2 = (lane & 3) * 2;
    const int r1 = g + 8;
    const int rh0 = g >> 3, rw0 = g & 7, rh1 = r1 >> 3, rw1 = r1 & 7;
    #pragma unroll
    for (int j16 = 0; j16 < 4; ++j16)
        #pragma unroll
        for (int h = 0; h < 2; ++h) {
            int cb = (j16 * 2 + h) * 8 + n2;
            #pragma unroll
            for (int e = 0; e < 2; ++e) {
                int col = cb + e;
                int ch = col >> 3, cw = col & 7;
                s[j16][h][e]     += srp[(rh0 - ch + 7) * 15 + (rw0 - cw + 7)]
                                  + smask[g * 65 + col];
                s[j16][h][2 + e] += srp[(rh1 - ch + 7) * 15 + (rw1 - cw + 7)]
                                  + smask[r1 * 65 + col];
            }
        }

    // ---- softmax (full row available; quad-shfl reduce) ----
    float m0 = -1e30f, m1 = -1e30f;
    #pragma unroll
    for (int j16 = 0; j16 < 4; ++j16)
        #pragma unroll
        for (int h = 0; h < 2; ++h) {
            m0 = fmaxf(m0, fmaxf(s[j16][h][0], s[j16][h][1]));
            m1 = fmaxf(m1, fmaxf(s[j16][h][2], s[j16][h][3]));
        }
    m0 = fmaxf(m0, __shfl_xor_sync(0xffffffffu, m0, 1));
    m0 = fmaxf(m0, __shfl_xor_sync(0xffffffffu, m0, 2));
    m1 = fmaxf(m1, __shfl_xor_sync(0xffffffffu, m1, 1));
    m1 = fmaxf(m1, __shfl_xor_sync(0xffffffffu, m1, 2));

    float t0 = 0.f, t1 = 0.f;
    #pragma unroll
    for (int j16 = 0; j16 < 4; ++j16)
        #pragma unroll
        for (int h = 0; h < 2; ++h) {
            s[j16][h][0] = ex2((s[j16][h][0] - m0) * LOG2E);
            s[j16][h][1] = ex2((s[j16][h][1] - m0) * LOG2E);
            s[j16][h][2] = ex2((s[j16][h][2] - m1) * LOG2E);
            s[j16][h][3] = ex2((s[j16][h][3] - m1) * LOG2E);
            t0 += s[j16][h][0] + s[j16][h][1];
            t1 += s[j16][h][2] + s[j16][h][3];
        }
    t0 += __shfl_xor_sync(0xffffffffu, t0, 1);
    t0 += __shfl_xor_sync(0xffffffffu, t0, 2);
    t1 += __shfl_xor_sync(0xffffffffu, t1, 1);
    t1 += __shfl_xor_sync(0xffffffffu, t1, 2);
    const float inv0 = 1.f / t0, inv1 = 1.f / t1;

    // ---- pack P (with 1/sum folded) to bf16 hi/lo A-frags ----
    uint32_t ph[4][4], pl[4][4];
    #pragma unroll
    for (int j16 = 0; j16 < 4; ++j16) {
        split2(s[j16][0][0] * inv0, s[j16][0][1] * inv0, ph[j16][0], pl[j16][0]);
        split2(s[j16][0][2] * inv1, s[j16][0][3] * inv1, ph[j16][1], pl[j16][1]);
        split2(s[j16][1][0] * inv0, s[j16][1][1] * inv0, ph[j16][2], pl[j16][2]);
        split2(s[j16][1][2] * inv1, s[j16][1][3] * inv1, ph[j16][3], pl[j16][3]);
    }

    // ---- O = P @ V (3-pass split), O tile 16x32 per warp ----
    float o[4][4];
    #pragma unroll
    for (int n8 = 0; n8 < 4; ++n8)
        #pragma unroll
        for (int e = 0; e < 4; ++e) o[n8][e] = 0.f;

    #pragma unroll
    for (int pass = 0; pass < 3; ++pass) {
        uint32_t bvb = sb + (pass == 1 ? OFVL : OFVH);
        #pragma unroll
        for (int ks = 0; ks < 4; ++ks) {
            const uint32_t* ap = (pass == 2) ? pl[ks] : ph[ks];
            #pragma unroll
            for (int n16 = 0; n16 < 2; ++n16) {
                uint32_t bv[4];
                LDSM4(bv, bvb + voff + n16 * (16 * VST * 2) + ks * 32);
                MMA16816(o[n16 * 2 + 0], ap, bv[0], bv[1]);
                MMA16816(o[n16 * 2 + 1], ap, bv[2], bv[3]);
            }
        }
    }

    // ---- write O fragments to g_att ----
    float* og = g_att + ((size_t)win * NTOK) * DIM + head * HD;
    #pragma unroll
    for (int n8 = 0; n8 < 4; ++n8) {
        int col = n8 * 8 + n2;
        *(float2*)&og[(size_t)g  * DIM + col] = make_float2(o[n8][0], o[n8][1]);
        *(float2*)&og[(size_t)r1 * DIM + col] = make_float2(o[n8][2], o[n8][3]);
    }
}

// ------------------------- launch -------------------------
extern "C" void kernel_launch(void* const* d_in, const int* in_sizes, int n_in,
                              void* d_out, int out_size)
{
    const float* x      = (const float*)d_in[0];
    const float* mask   = (const float*)d_in[1];
    const float* w_qkv  = (const float*)d_in[2];
    const float* b_qkv  = (const float*)d_in[3];
    const float* rpbt   = (const float*)d_in[4];
    const float* w_proj = (const float*)d_in[5];
    const float* b_proj = (const float*)d_in[6];
    float* out = (float*)d_out;

    void *p_qkv, *p_att, *p_wqh, *p_wql, *p_wph, *p_wpl, *p_bq;
    cudaGetSymbolAddress(&p_qkv, g_qkv);
    cudaGetSymbolAddress(&p_att, g_att);
    cudaGetSymbolAddress(&p_wqh, g_wqh);
    cudaGetSymbolAddress(&p_wql, g_wql);
    cudaGetSymbolAddress(&p_wph, g_wph);
    cudaGetSymbolAddress(&p_wpl, g_wpl);
    cudaGetSymbolAddress(&p_bq,  g_bq);

    cudaFuncSetAttribute(gemm_mma,
                         cudaFuncAttributeMaxDynamicSharedMemorySize, GSMEM);
    cudaFuncSetAttribute(attn_mma,
                         cudaFuncAttributeMaxDynamicSharedMemorySize, ATT_SMEM);

    prep_kernel<<<432, 256>>>(w_qkv, b_qkv, w_proj);

    gemm_mma<<<MTOT / MT, 256, GSMEM>>>(
        x, (const __nv_bfloat16*)p_wqh, (const __nv_bfloat16*)p_wql,
        (const float*)p_bq, (float*)p_qkv, QKVN, QKVN);

    dim3 agrid(NWIN, NH);
    attn_mma<<<agrid, 128, ATT_SMEM>>>(mask, rpbt);

    gemm_mma<<<MTOT / MT, 256, GSMEM>>>(
        (const float*)p_att, (const __nv_bfloat16*)p_wph, (const __nv_bfloat16*)p_wpl,
        b_proj, out, DIM, DIM);
}

// round 12
// speedup vs baseline: 1.4736x; 1.4736x over previous
#include <cuda_runtime.h>
#include <cuda_bf16.h>
#include <cstdint>

#define NTOK 64
#define DIM  192
#define NH   6
#define HD   32
#define NWIN 2048
#define MTOT (NWIN * NTOK)     // 131072
#define QKVN 576

// ------------------------- device scratch (static) -------------------------
__device__ float g_qkv[MTOT * QKVN];            // qkv output, fp32
__device__ float g_att[MTOT * DIM];             // attention output, fp32
__device__ __nv_bfloat16 g_wqh[QKVN * DIM];     // w_qkv^T hi (scaled q cols)
__device__ __nv_bfloat16 g_wql[QKVN * DIM];     // w_qkv^T lo
__device__ __nv_bfloat16 g_wph[DIM * DIM];      // w_proj^T hi
__device__ __nv_bfloat16 g_wpl[DIM * DIM];      // w_proj^T lo
__device__ float g_bq[QKVN];                    // qkv bias (scaled q part)

__device__ __forceinline__ uint32_t smem_u32(const void* p) {
    uint32_t a;
    asm("{ .reg .u64 t; cvta.to.shared.u64 t, %1; cvt.u32.u64 %0, t; }"
        : "=r"(a) : "l"(p));
    return a;
}
__device__ __forceinline__ uint32_t pkbf(__nv_bfloat16 a, __nv_bfloat16 b) {
    return (uint32_t)__bfloat16_as_ushort(a)
         | ((uint32_t)__bfloat16_as_ushort(b) << 16);
}
__device__ __forceinline__ float ex2(float x) {
    float y; asm("ex2.approx.ftz.f32 %0, %1;" : "=f"(y) : "f"(x)); return y;
}
__device__ __forceinline__ void split2(float a, float b, uint32_t& hi, uint32_t& lo) {
    __nv_bfloat16 ha = __float2bfloat16(a);
    __nv_bfloat16 hb = __float2bfloat16(b);
    hi = pkbf(ha, hb);
    lo = pkbf(__float2bfloat16(a - __bfloat162float(ha)),
              __float2bfloat16(b - __bfloat162float(hb)));
}
__device__ __forceinline__ void cp16(uint32_t daddr, const void* src) {
    asm volatile("cp.async.cg.shared.global [%0], [%1], 16;"
                 :: "r"(daddr), "l"(src));
}
#define CP_COMMIT() asm volatile("cp.async.commit_group;" ::: "memory")
#define CP_WAIT0()  asm volatile("cp.async.wait_group 0;" ::: "memory")

#define LDSM4(r, addr)                                                      \
    asm volatile("ldmatrix.sync.aligned.m8n8.x4.shared.b16 "                \
                 "{%0,%1,%2,%3}, [%4];"                                     \
                 : "=r"((r)[0]), "=r"((r)[1]), "=r"((r)[2]), "=r"((r)[3])   \
                 : "r"(addr))

#define MMA16816(c, a, b0, b1)                                              \
    asm volatile("mma.sync.aligned.m16n8k16.row.col.f32.bf16.bf16.f32 "     \
                 "{%0,%1,%2,%3}, {%4,%5,%6,%7}, {%8,%9}, {%0,%1,%2,%3};"    \
                 : "+f"((c)[0]), "+f"((c)[1]), "+f"((c)[2]), "+f"((c)[3])   \
                 : "r"((a)[0]), "r"((a)[1]), "r"((a)[2]), "r"((a)[3]),      \
                   "r"(b0), "r"(b1))

// ------------------------- prep: split + transpose weights -------------------------
__global__ void prep_kernel(const float* __restrict__ wqkv,
                            const float* __restrict__ bqkv,
                            const float* __restrict__ wproj)
{
    const float SCALE = 0.17677669529663689f;
    int i = blockIdx.x * 256 + threadIdx.x;
    if (i < QKVN * DIM) {
        int n = i % QKVN, k = i / QKVN;
        float v = wqkv[k * QKVN + n];
        if (n < DIM) v *= SCALE;
        __nv_bfloat16 h = __float2bfloat16(v);
        g_wqh[n * DIM + k] = h;
        g_wql[n * DIM + k] = __float2bfloat16(v - __bfloat162float(h));
    }
    if (i < DIM * DIM) {
        int n = i % DIM, k = i / DIM;
        float v = wproj[k * DIM + n];
        __nv_bfloat16 h = __float2bfloat16(v);
        g_wph[n * DIM + k] = h;
        g_wpl[n * DIM + k] = __float2bfloat16(v - __bfloat162float(h));
    }
    if (i < QKVN) g_bq[i] = (i < DIM) ? bqkv[i] * SCALE : bqkv[i];
}

// --------- mma.sync bf16-split GEMM, cp.async double-buffered B ----------
#define MT   128
#define KD   192
#define ASTR 200
#define BSTR 200
#define CSTR 68
#define OFF_AH 0
#define OFF_AL 51200
#define OFF_B0 102400           // buffer: BH at +0, BL at +25600 (51200 total)
#define OFF_B1 153600
#define GSMEM  204800

__global__ __launch_bounds__(256, 1)
void gemm_mma(const float* __restrict__ A,
              const __nv_bfloat16* __restrict__ Bh,
              const __nv_bfloat16* __restrict__ Bl,
              const float* __restrict__ bias,
              float* __restrict__ C,
              int ldc, int ntot)
{
    extern __shared__ char smem[];
    __nv_bfloat16* sAh = (__nv_bfloat16*)(smem + OFF_AH);
    __nv_bfloat16* sAl = (__nv_bfloat16*)(smem + OFF_AL);
    const uint32_t sb  = smem_u32(smem);

    const int tid  = threadIdx.x;
    const int wid  = tid >> 5;
    const int lane = tid & 31;
    const int wm   = wid >> 1;
    const int wn   = wid & 1;

    // ---- prefetch chunk 0 B tiles via cp.async ----
    {
        uint32_t dstb = sb + OFF_B0;
        #pragma unroll
        for (int s2 = 0; s2 < 2; ++s2) {
            const __nv_bfloat16* src = s2 ? Bl : Bh;   // chunk 0: offset 0
            #pragma unroll
            for (int q = 0; q < 6; ++q) {
                int g = tid + q * 256;
                int row = g / 24, gg = g % 24;
                cp16(dstb + s2 * 25600 + (uint32_t)(row * BSTR + gg * 8) * 2u,
                     src + (size_t)row * KD + gg * 8);
            }
        }
        CP_COMMIT();
    }

    // ---- stage A (128x192 fp32 -> bf16 hi/lo in SMEM) ----
    {
        const float* ag = A + (size_t)blockIdx.x * MT * KD;
        #pragma unroll
        for (int q = 0; q < 24; ++q) {
            int f  = tid + q * 256;
            int r  = f / 48, c4 = (f % 48) * 4;
            float4 v = *(const float4*)&ag[(size_t)r * KD + c4];
            uint2 hp, lp;
            split2(v.x, v.y, hp.x, lp.x);
            split2(v.z, v.w, hp.y, lp.y);
            *(uint2*)&sAh[r * ASTR + c4] = hp;
            *(uint2*)&sAl[r * ASTR + c4] = lp;
        }
    }

    const int asub = lane >> 3, ar = lane & 7;
    uint32_t aeo[2], beo[2];
    #pragma unroll
    for (int t = 0; t < 2; ++t) {
        int row = wm * 32 + t * 16 + ar + (asub & 1) * 8;
        int col = (asub >> 1) * 8;
        aeo[t] = (uint32_t)(row * ASTR + col) * 2u;
    }
    #pragma unroll
    for (int p = 0; p < 2; ++p) {
        int row = wn * 32 + p * 16 + ar + (asub >> 1) * 8;
        int col = (asub & 1) * 8;
        beo[p] = (uint32_t)(row * BSTR + col) * 2u;
    }

    const int nchunks = ntot / 64;
    #pragma unroll 1
    for (int nc = 0; nc < nchunks; ++nc) {
        CP_WAIT0();
        __syncthreads();   // current B buffer ready; A ready (iter 0); sC reads done

        // ---- prefetch next chunk into the other buffer ----
        if (nc + 1 < nchunks) {
            uint32_t dstb = sb + (((nc + 1) & 1) ? OFF_B1 : OFF_B0);
            #pragma unroll
            for (int s2 = 0; s2 < 2; ++s2) {
                const __nv_bfloat16* src =
                    (s2 ? Bl : Bh) + (size_t)((nc + 1) * 64) * KD;
                #pragma unroll
                for (int q = 0; q < 6; ++q) {
                    int g = tid + q * 256;
                    int row = g / 24, gg = g % 24;
                    cp16(dstb + s2 * 25600 + (uint32_t)(row * BSTR + gg * 8) * 2u,
                         src + (size_t)row * KD + gg * 8);
                }
            }
            CP_COMMIT();
        }

        const uint32_t bufb = sb + ((nc & 1) ? OFF_B1 : OFF_B0);

        float c[2][4][4];
        #pragma unroll
        for (int t = 0; t < 2; ++t)
            #pragma unroll
            for (int f = 0; f < 4; ++f)
                #pragma unroll
                for (int j = 0; j < 4; ++j) c[t][f][j] = 0.f;

        #pragma unroll 1
        for (int s = 0; s < 3; ++s) {
            uint32_t ab = sb + (s == 2 ? OFF_AL : OFF_AH);
            uint32_t bb = bufb + (s == 1 ? 25600u : 0u);
            #pragma unroll
            for (int k16 = 0; k16 < 12; ++k16) {
                uint32_t ko = (uint32_t)k16 * 32u;
                uint32_t a[2][4], bf[2][4];
                LDSM4(a[0], ab + aeo[0] + ko);
                LDSM4(a[1], ab + aeo[1] + ko);
                LDSM4(bf[0], bb + beo[0] + ko);
                LDSM4(bf[1], bb + beo[1] + ko);
                #pragma unroll
                for (int t = 0; t < 2; ++t) {
                    MMA16816(c[t][0], a[t], bf[0][0], bf[0][1]);
                    MMA16816(c[t][1], a[t], bf[0][2], bf[0][3]);
                    MMA16816(c[t][2], a[t], bf[1][0], bf[1][1]);
                    MMA16816(c[t][3], a[t], bf[1][2], bf[1][3]);
                }
            }
        }
        __syncthreads();   // all reads of this B buffer done -> alias it as sC

        float* sC = (float*)(smem + ((nc & 1) ? OFF_B1 : OFF_B0));
        #pragma unroll
        for (int t = 0; t < 2; ++t) {
            int r0 = wm * 32 + t * 16 + (lane >> 2);
            #pragma unroll
            for (int f = 0; f < 4; ++f) {
                int cc = wn * 32 + f * 8 + (lane & 3) * 2;
                sC[r0 * CSTR + cc]           = c[t][f][0];
                sC[r0 * CSTR + cc + 1]       = c[t][f][1];
                sC[(r0 + 8) * CSTR + cc]     = c[t][f][2];
                sC[(r0 + 8) * CSTR + cc + 1] = c[t][f][3];
            }
        }
        __syncthreads();

        const int n0 = nc * 64;
        float* crow = C + (size_t)blockIdx.x * MT * ldc + n0;
        #pragma unroll
        for (int q = 0; q < 8; ++q) {
            int f = tid + q * 256;
            int r = f >> 4, c4 = (f & 15) * 4;
            float4 v = *(float4*)&sC[r * CSTR + c4];
            v.x += __ldg(&bias[n0 + c4 + 0]);
            v.y += __ldg(&bias[n0 + c4 + 1]);
            v.z += __ldg(&bias[n0 + c4 + 2]);
            v.w += __ldg(&bias[n0 + c4 + 3]);
            *(float4*)&crow[(size_t)r * ldc + c4] = v;
        }
        // top-of-loop __syncthreads orders these sC reads before the next
        // prefetch that overwrites this buffer (issued in iteration nc+1).
    }
}

// -------- FA-style tensor-core attention: CTA per window, loop 6 heads --------
#define QST 40
#define VST 72
#define OFQH 0
#define OFQL (OFQH + 64 * QST * 2)     // 5120
#define OFKH (OFQL + 64 * QST * 2)     // 10240
#define OFKL (OFKH + 64 * QST * 2)     // 15360
#define OFVH (OFKL + 64 * QST * 2)     // 20480
#define OFVL (OFVH + 32 * VST * 2)     // 25088
#define OFMSK (OFVL + 32 * VST * 2)    // 29696
#define OFRP  (OFMSK + 64 * 65 * 4)    // 46336: [head][228]
#define ATT_SMEM (OFRP + 6 * 228 * 4)  // 51808

__global__ __launch_bounds__(128, 4)
void attn_mma(const float* __restrict__ mask,
              const float* __restrict__ rpbt)
{
    extern __shared__ char smem[];
    const uint32_t sb = smem_u32(smem);
    float* smask = (float*)(smem + OFMSK);
    float* srp   = (float*)(smem + OFRP);

    const int tid  = threadIdx.x;
    const int wid  = tid >> 5;
    const int lane = tid & 31;
    const int win  = blockIdx.x;
    const float LOG2E = 1.4426950408889634f;

    // ---- stage mask (fp32, stride 65) + rpbt all heads, once per window ----
    {
        const float* mg = mask + (size_t)(win & 63) * (NTOK * NTOK);
        #pragma unroll
        for (int q = 0; q < 8; ++q) {
            int f = tid + q * 128;
            int r = f >> 4, c = (f & 15) * 4;
            float4 v = *(const float4*)&mg[r * 64 + c];
            smask[r * 65 + c + 0] = v.x; smask[r * 65 + c + 1] = v.y;
            smask[r * 65 + c + 2] = v.z; smask[r * 65 + c + 3] = v.w;
        }
        for (int f = tid; f < 225 * NH; f += 128)   // f = idx*6 + head
            srp[(f % NH) * 228 + f / NH] = __ldg(&rpbt[f]);
    }

    // per-warp fragment offsets (same conventions as gemm)
    const int asub = lane >> 3, ar = lane & 7;
    const uint32_t aqoff =
        (uint32_t)((wid * 16 + ar + (asub & 1) * 8) * QST + (asub >> 1) * 8) * 2u;
    const uint32_t koff =
        (uint32_t)((ar + (asub >> 1) * 8) * QST + (asub & 1) * 8) * 2u;
    const uint32_t voff =
        (uint32_t)((ar + (asub >> 1) * 8) * VST + (asub & 1) * 8) * 2u;

    const int g  = wid * 16 + (lane >> 2);
    const int n2 = (lane & 3) * 2;
    const int r1 = g + 8;
    const int rh0 = g >> 3, rw0 = g & 7, rh1 = r1 >> 3, rw1 = r1 & 7;

    #pragma unroll 1
    for (int head = 0; head < NH; ++head) {
        __syncthreads();   // prior head's smem reads done; mask/rp visible (iter 0)

        const float* base = g_qkv + (size_t)win * (NTOK * QKVN) + head * HD;

        // ---- stage Q, K (split bf16, stride 40) ----
        #pragma unroll
        for (int q = 0; q < 4; ++q) {
            int f = tid + q * 128;
            int r = f >> 3, c4 = (f & 7) * 4;
            const float* src = base + (size_t)r * QKVN + c4;
            float4 vq = *(const float4*)src;
            float4 vk = *(const float4*)(src + 192);
            uint2 h, l;
            split2(vq.x, vq.y, h.x, l.x); split2(vq.z, vq.w, h.y, l.y);
            *(uint2*)(smem + OFQH + (r * QST + c4) * 2) = h;
            *(uint2*)(smem + OFQL + (r * QST + c4) * 2) = l;
            split2(vk.x, vk.y, h.x, l.x); split2(vk.z, vk.w, h.y, l.y);
            *(uint2*)(smem + OFKH + (r * QST + c4) * 2) = h;
            *(uint2*)(smem + OFKL + (r * QST + c4) * 2) = l;
        }
        // ---- stage V transposed (32 x 64, stride 72) ----
        #pragma unroll
        for (int q = 0; q < 4; ++q) {
            int f = tid + q * 128;
            int r = f >> 3, c4 = (f & 7) * 4;
            float4 v = *(const float4*)(base + (size_t)r * QKVN + 384 + c4);
            #pragma unroll
            for (int i = 0; i < 4; ++i) {
                float x = (i == 0) ? v.x : (i == 1) ? v.y : (i == 2) ? v.z : v.w;
                __nv_bfloat16 h = __float2bfloat16(x);
                *(__nv_bfloat16*)(smem + OFVH + ((c4 + i) * VST + r) * 2) = h;
                *(__nv_bfloat16*)(smem + OFVL + ((c4 + i) * VST + r) * 2) =
                    __float2bfloat16(x - __bfloat162float(h));
            }
        }
        __syncthreads();

        // ---- S = Q @ K^T (3-pass split), 16x64 per warp ----
        float s[4][2][4];
        #pragma unroll
        for (int j = 0; j < 4; ++j)
            #pragma unroll
            for (int h = 0; h < 2; ++h)
                #pragma unroll
                for (int e = 0; e < 4; ++e) s[j][h][e] = 0.f;

        #pragma unroll
        for (int pass = 0; pass < 3; ++pass) {
            uint32_t ab = sb + (pass == 2 ? OFQL : OFQH);
            uint32_t bb = sb + (pass == 1 ? OFKL : OFKH);
            #pragma unroll
            for (int ks = 0; ks < 2; ++ks) {
                uint32_t aq[4];
                LDSM4(aq, ab + aqoff + ks * 32);
                #pragma unroll
                for (int j16 = 0; j16 < 4; ++j16) {
                    uint32_t bk[4];
                    LDSM4(bk, bb + koff + j16 * (16 * QST * 2) + ks * 32);
                    MMA16816(s[j16][0], aq, bk[0], bk[1]);
                    MMA16816(s[j16][1], aq, bk[2], bk[3]);
                }
            }
        }

        // ---- bias + mask on fragments ----
        const float* rp = srp + head * 228;
        #pragma unroll
        for (int j16 = 0; j16 < 4; ++j16)
            #pragma unroll
            for (int h = 0; h < 2; ++h) {
                int cb = (j16 * 2 + h) * 8 + n2;
                #pragma unroll
                for (int e = 0; e < 2; ++e) {
                    int col = cb + e;
                    int ch = col >> 3, cw = col & 7;
                    s[j16][h][e]     += rp[(rh0 - ch + 7) * 15 + (rw0 - cw + 7)]
                                      + smask[g * 65 + col];
                    s[j16][h][2 + e] += rp[(rh1 - ch + 7) * 15 + (rw1 - cw + 7)]
                                      + smask[r1 * 65 + col];
                }
            }

        // ---- softmax (quad-shfl reduce) ----
        float m0 = -1e30f, m1 = -1e30f;
        #pragma unroll
        for (int j16 = 0; j16 < 4; ++j16)
            #pragma unroll
            for (int h = 0; h < 2; ++h) {
                m0 = fmaxf(m0, fmaxf(s[j16][h][0], s[j16][h][1]));
                m1 = fmaxf(m1, fmaxf(s[j16][h][2], s[j16][h][3]));
            }
        m0 = fmaxf(m0, __shfl_xor_sync(0xffffffffu, m0, 1));
        m0 = fmaxf(m0, __shfl_xor_sync(0xffffffffu, m0, 2));
        m1 = fmaxf(m1, __shfl_xor_sync(0xffffffffu, m1, 1));
        m1 = fmaxf(m1, __shfl_xor_sync(0xffffffffu, m1, 2));

        float t0 = 0.f, t1 = 0.f;
        #pragma unroll
        for (int j16 = 0; j16 < 4; ++j16)
            #pragma unroll
            for (int h = 0; h < 2; ++h) {
                s[j16][h][0] = ex2((s[j16][h][0] - m0) * LOG2E);
                s[j16][h][1] = ex2((s[j16][h][1] - m0) * LOG2E);
                s[j16][h][2] = ex2((s[j16][h][2] - m1) * LOG2E);
                s[j16][h][3] = ex2((s[j16][h][3] - m1) * LOG2E);
                t0 += s[j16][h][0] + s[j16][h][1];
                t1 += s[j16][h][2] + s[j16][h][3];
            }
        t0 += __shfl_xor_sync(0xffffffffu, t0, 1);
        t0 += __shfl_xor_sync(0xffffffffu, t0, 2);
        t1 += __shfl_xor_sync(0xffffffffu, t1, 1);
        t1 += __shfl_xor_sync(0xffffffffu, t1, 2);
        const float inv0 = 1.f / t0, inv1 = 1.f / t1;

        // ---- pack P (1/sum folded) to bf16 hi/lo A-frags ----
        uint32_t ph[4][4], pl[4][4];
        #pragma unroll
        for (int j16 = 0; j16 < 4; ++j16) {
            split2(s[j16][0][0] * inv0, s[j16][0][1] * inv0, ph[j16][0], pl[j16][0]);
            split2(s[j16][0][2] * inv1, s[j16][0][3] * inv1, ph[j16][1], pl[j16][1]);
            split2(s[j16][1][0] * inv0, s[j16][1][1] * inv0, ph[j16][2], pl[j16][2]);
            split2(s[j16][1][2] * inv1, s[j16][1][3] * inv1, ph[j16][3], pl[j16][3]);
        }

        // ---- O = P @ V (3-pass split), 16x32 per warp ----
        float o[4][4];
        #pragma unroll
        for (int n8 = 0; n8 < 4; ++n8)
            #pragma unroll
            for (int e = 0; e < 4; ++e) o[n8][e] = 0.f;

        #pragma unroll
        for (int pass = 0; pass < 3; ++pass) {
            uint32_t bvb = sb + (pass == 1 ? OFVL : OFVH);
            #pragma unroll
            for (int ks = 0; ks < 4; ++ks) {
                const uint32_t* ap = (pass == 2) ? pl[ks] : ph[ks];
                #pragma unroll
                for (int n16 = 0; n16 < 2; ++n16) {
                    uint32_t bv[4];
                    LDSM4(bv, bvb + voff + n16 * (16 * VST * 2) + ks * 32);
                    MMA16816(o[n16 * 2 + 0], ap, bv[0], bv[1]);
                    MMA16816(o[n16 * 2 + 1], ap, bv[2], bv[3]);
                }
            }
        }

        // ---- write O fragments ----
        float* og = g_att + ((size_t)win * NTOK) * DIM + head * HD;
        #pragma unroll
        for (int n8 = 0; n8 < 4; ++n8) {
            int col = n8 * 8 + n2;
            *(float2*)&og[(size_t)g  * DIM + col] = make_float2(o[n8][0], o[n8][1]);
            *(float2*)&og[(size_t)r1 * DIM + col] = make_float2(o[n8][2], o[n8][3]);
        }
    }
}

// ------------------------- launch -------------------------
extern "C" void kernel_launch(void* const* d_in, const int* in_sizes, int n_in,
                              void* d_out, int out_size)
{
    const float* x      = (const float*)d_in[0];
    const float* mask   = (const float*)d_in[1];
    const float* w_qkv  = (const float*)d_in[2];
    const float* b_qkv  = (const float*)d_in[3];
    const float* rpbt   = (const float*)d_in[4];
    const float* w_proj = (const float*)d_in[5];
    const float* b_proj = (const float*)d_in[6];
    float* out = (float*)d_out;

    void *p_qkv, *p_att, *p_wqh, *p_wql, *p_wph, *p_wpl, *p_bq;
    cudaGetSymbolAddress(&p_qkv, g_qkv);
    cudaGetSymbolAddress(&p_att, g_att);
    cudaGetSymbolAddress(&p_wqh, g_wqh);
    cudaGetSymbolAddress(&p_wql, g_wql);
    cudaGetSymbolAddress(&p_wph, g_wph);
    cudaGetSymbolAddress(&p_wpl, g_wpl);
    cudaGetSymbolAddress(&p_bq,  g_bq);

    cudaFuncSetAttribute(gemm_mma,
                         cudaFuncAttributeMaxDynamicSharedMemorySize, GSMEM);
    cudaFuncSetAttribute(attn_mma,
                         cudaFuncAttributeMaxDynamicSharedMemorySize, ATT_SMEM);

    prep_kernel<<<432, 256>>>(w_qkv, b_qkv, w_proj);

    gemm_mma<<<MTOT / MT, 256, GSMEM>>>(
        x, (const __nv_bfloat16*)p_wqh, (const __nv_bfloat16*)p_wql,
        (const float*)p_bq, (float*)p_qkv, QKVN, QKVN);

    attn_mma<<<NWIN, 128, ATT_SMEM>>>(mask, rpbt);

    gemm_mma<<<MTOT / MT, 256, GSMEM>>>(
        (const float*)p_att, (const __nv_bfloat16*)p_wph, (const __nv_bfloat16*)p_wpl,
        b_proj, out, DIM, DIM);
}

// round 13
// speedup vs baseline: 1.5810x; 1.0729x over previous
#include <cuda_runtime.h>
#include <cuda_bf16.h>
#include <cstdint>

#define NTOK 64
#define DIM  192
#define NH   6
#define HD   32
#define NWIN 2048
#define MTOT (NWIN * NTOK)     // 131072
#define QKVN 576

// ------------------------- device scratch (static) -------------------------
__device__ __nv_bfloat16 g_qh[MTOT * QKVN];     // qkv output bf16 hi
__device__ __nv_bfloat16 g_ql[MTOT * QKVN];     // qkv output bf16 lo
__device__ float g_att[MTOT * DIM];             // attention output, fp32
__device__ __nv_bfloat16 g_wqh[QKVN * DIM];     // w_qkv^T hi (scaled q cols)
__device__ __nv_bfloat16 g_wql[QKVN * DIM];     // w_qkv^T lo
__device__ __nv_bfloat16 g_wph[DIM * DIM];      // w_proj^T hi
__device__ __nv_bfloat16 g_wpl[DIM * DIM];      // w_proj^T lo
__device__ float g_bq[QKVN];                    // qkv bias (scaled q part)

__device__ __forceinline__ uint32_t smem_u32(const void* p) {
    uint32_t a;
    asm("{ .reg .u64 t; cvta.to.shared.u64 t, %1; cvt.u32.u64 %0, t; }"
        : "=r"(a) : "l"(p));
    return a;
}
__device__ __forceinline__ uint32_t pkbf(__nv_bfloat16 a, __nv_bfloat16 b) {
    return (uint32_t)__bfloat16_as_ushort(a)
         | ((uint32_t)__bfloat16_as_ushort(b) << 16);
}
__device__ __forceinline__ float ex2(float x) {
    float y; asm("ex2.approx.ftz.f32 %0, %1;" : "=f"(y) : "f"(x)); return y;
}
__device__ __forceinline__ void split2(float a, float b, uint32_t& hi, uint32_t& lo) {
    __nv_bfloat16 ha = __float2bfloat16(a);
    __nv_bfloat16 hb = __float2bfloat16(b);
    hi = pkbf(ha, hb);
    lo = pkbf(__float2bfloat16(a - __bfloat162float(ha)),
              __float2bfloat16(b - __bfloat162float(hb)));
}
__device__ __forceinline__ void cp16(uint32_t daddr, const void* src) {
    asm volatile("cp.async.cg.shared.global [%0], [%1], 16;"
                 :: "r"(daddr), "l"(src));
}
#define CP_COMMIT() asm volatile("cp.async.commit_group;" ::: "memory")
#define CP_WAIT0()  asm volatile("cp.async.wait_group 0;" ::: "memory")

#define LDSM4(r, addr)                                                      \
    asm volatile("ldmatrix.sync.aligned.m8n8.x4.shared.b16 "                \
                 "{%0,%1,%2,%3}, [%4];"                                     \
                 : "=r"((r)[0]), "=r"((r)[1]), "=r"((r)[2]), "=r"((r)[3])   \
                 : "r"(addr))

#define LDSM4T(r, addr)                                                     \
    asm volatile("ldmatrix.sync.aligned.m8n8.x4.trans.shared.b16 "          \
                 "{%0,%1,%2,%3}, [%4];"                                     \
                 : "=r"((r)[0]), "=r"((r)[1]), "=r"((r)[2]), "=r"((r)[3])   \
                 : "r"(addr))

#define MMA16816(c, a, b0, b1)                                              \
    asm volatile("mma.sync.aligned.m16n8k16.row.col.f32.bf16.bf16.f32 "     \
                 "{%0,%1,%2,%3}, {%4,%5,%6,%7}, {%8,%9}, {%0,%1,%2,%3};"    \
                 : "+f"((c)[0]), "+f"((c)[1]), "+f"((c)[2]), "+f"((c)[3])   \
                 : "r"((a)[0]), "r"((a)[1]), "r"((a)[2]), "r"((a)[3]),      \
                   "r"(b0), "r"(b1))

// ------------------------- prep: split + transpose weights -------------------------
__global__ void prep_kernel(const float* __restrict__ wqkv,
                            const float* __restrict__ bqkv,
                            const float* __restrict__ wproj)
{
    const float SCALE = 0.17677669529663689f;
    int i = blockIdx.x * 256 + threadIdx.x;
    if (i < QKVN * DIM) {
        int n = i % QKVN, k = i / QKVN;
        float v = wqkv[k * QKVN + n];
        if (n < DIM) v *= SCALE;
        __nv_bfloat16 h = __float2bfloat16(v);
        g_wqh[n * DIM + k] = h;
        g_wql[n * DIM + k] = __float2bfloat16(v - __bfloat162float(h));
    }
    if (i < DIM * DIM) {
        int n = i % DIM, k = i / DIM;
        float v = wproj[k * DIM + n];
        __nv_bfloat16 h = __float2bfloat16(v);
        g_wph[n * DIM + k] = h;
        g_wpl[n * DIM + k] = __float2bfloat16(v - __bfloat162float(h));
    }
    if (i < QKVN) g_bq[i] = (i < DIM) ? bqkv[i] * SCALE : bqkv[i];
}

// --------- mma.sync bf16-split GEMM, cp.async double-buffered B ----------
// If Ch != nullptr, epilogue writes split bf16 (Ch/Cl); else fp32 C.
#define MT   128
#define KD   192
#define ASTR 200
#define BSTR 200
#define CSTR 68
#define OFF_AH 0
#define OFF_AL 51200
#define OFF_B0 102400
#define OFF_B1 153600
#define GSMEM  204800

__global__ __launch_bounds__(256, 1)
void gemm_mma(const float* __restrict__ A,
              const __nv_bfloat16* __restrict__ Bh,
              const __nv_bfloat16* __restrict__ Bl,
              const float* __restrict__ bias,
              float* __restrict__ C,
              __nv_bfloat16* __restrict__ Ch,
              __nv_bfloat16* __restrict__ Cl,
              int ldc, int ntot)
{
    extern __shared__ char smem[];
    __nv_bfloat16* sAh = (__nv_bfloat16*)(smem + OFF_AH);
    __nv_bfloat16* sAl = (__nv_bfloat16*)(smem + OFF_AL);
    const uint32_t sb  = smem_u32(smem);

    const int tid  = threadIdx.x;
    const int wid  = tid >> 5;
    const int lane = tid & 31;
    const int wm   = wid >> 1;
    const int wn   = wid & 1;

    // ---- prefetch chunk 0 B tiles via cp.async ----
    {
        uint32_t dstb = sb + OFF_B0;
        #pragma unroll
        for (int s2 = 0; s2 < 2; ++s2) {
            const __nv_bfloat16* src = s2 ? Bl : Bh;
            #pragma unroll
            for (int q = 0; q < 6; ++q) {
                int g = tid + q * 256;
                int row = g / 24, gg = g % 24;
                cp16(dstb + s2 * 25600 + (uint32_t)(row * BSTR + gg * 8) * 2u,
                     src + (size_t)row * KD + gg * 8);
            }
        }
        CP_COMMIT();
    }

    // ---- stage A (128x192 fp32 -> bf16 hi/lo in SMEM) ----
    {
        const float* ag = A + (size_t)blockIdx.x * MT * KD;
        #pragma unroll
        for (int q = 0; q < 24; ++q) {
            int f  = tid + q * 256;
            int r  = f / 48, c4 = (f % 48) * 4;
            float4 v = *(const float4*)&ag[(size_t)r * KD + c4];
            uint2 hp, lp;
            split2(v.x, v.y, hp.x, lp.x);
            split2(v.z, v.w, hp.y, lp.y);
            *(uint2*)&sAh[r * ASTR + c4] = hp;
            *(uint2*)&sAl[r * ASTR + c4] = lp;
        }
    }

    const int asub = lane >> 3, ar = lane & 7;
    uint32_t aeo[2], beo[2];
    #pragma unroll
    for (int t = 0; t < 2; ++t) {
        int row = wm * 32 + t * 16 + ar + (asub & 1) * 8;
        int col = (asub >> 1) * 8;
        aeo[t] = (uint32_t)(row * ASTR + col) * 2u;
    }
    #pragma unroll
    for (int p = 0; p < 2; ++p) {
        int row = wn * 32 + p * 16 + ar + (asub >> 1) * 8;
        int col = (asub & 1) * 8;
        beo[p] = (uint32_t)(row * BSTR + col) * 2u;
    }

    const int nchunks = ntot / 64;
    #pragma unroll 1
    for (int nc = 0; nc < nchunks; ++nc) {
        CP_WAIT0();
        __syncthreads();

        if (nc + 1 < nchunks) {
            uint32_t dstb = sb + (((nc + 1) & 1) ? OFF_B1 : OFF_B0);
            #pragma unroll
            for (int s2 = 0; s2 < 2; ++s2) {
                const __nv_bfloat16* src =
                    (s2 ? Bl : Bh) + (size_t)((nc + 1) * 64) * KD;
                #pragma unroll
                for (int q = 0; q < 6; ++q) {
                    int g = tid + q * 256;
                    int row = g / 24, gg = g % 24;
                    cp16(dstb + s2 * 25600 + (uint32_t)(row * BSTR + gg * 8) * 2u,
                         src + (size_t)row * KD + gg * 8);
                }
            }
            CP_COMMIT();
        }

        const uint32_t bufb = sb + ((nc & 1) ? OFF_B1 : OFF_B0);

        float c[2][4][4];
        #pragma unroll
        for (int t = 0; t < 2; ++t)
            #pragma unroll
            for (int f = 0; f < 4; ++f)
                #pragma unroll
                for (int j = 0; j < 4; ++j) c[t][f][j] = 0.f;

        #pragma unroll 1
        for (int s = 0; s < 3; ++s) {
            uint32_t ab = sb + (s == 2 ? OFF_AL : OFF_AH);
            uint32_t bb = bufb + (s == 1 ? 25600u : 0u);
            #pragma unroll
            for (int k16 = 0; k16 < 12; ++k16) {
                uint32_t ko = (uint32_t)k16 * 32u;
                uint32_t a[2][4], bf[2][4];
                LDSM4(a[0], ab + aeo[0] + ko);
                LDSM4(a[1], ab + aeo[1] + ko);
                LDSM4(bf[0], bb + beo[0] + ko);
                LDSM4(bf[1], bb + beo[1] + ko);
                #pragma unroll
                for (int t = 0; t < 2; ++t) {
                    MMA16816(c[t][0], a[t], bf[0][0], bf[0][1]);
                    MMA16816(c[t][1], a[t], bf[0][2], bf[0][3]);
                    MMA16816(c[t][2], a[t], bf[1][0], bf[1][1]);
                    MMA16816(c[t][3], a[t], bf[1][2], bf[1][3]);
                }
            }
        }
        __syncthreads();

        float* sC = (float*)(smem + ((nc & 1) ? OFF_B1 : OFF_B0));
        #pragma unroll
        for (int t = 0; t < 2; ++t) {
            int r0 = wm * 32 + t * 16 + (lane >> 2);
            #pragma unroll
            for (int f = 0; f < 4; ++f) {
                int cc = wn * 32 + f * 8 + (lane & 3) * 2;
                sC[r0 * CSTR + cc]           = c[t][f][0];
                sC[r0 * CSTR + cc + 1]       = c[t][f][1];
                sC[(r0 + 8) * CSTR + cc]     = c[t][f][2];
                sC[(r0 + 8) * CSTR + cc + 1] = c[t][f][3];
            }
        }
        __syncthreads();

        const int n0 = nc * 64;
        if (Ch) {
            #pragma unroll
            for (int q = 0; q < 8; ++q) {
                int f = tid + q * 256;
                int r = f >> 4, c4 = (f & 15) * 4;
                float4 v = *(float4*)&sC[r * CSTR + c4];
                v.x += __ldg(&bias[n0 + c4 + 0]);
                v.y += __ldg(&bias[n0 + c4 + 1]);
                v.z += __ldg(&bias[n0 + c4 + 2]);
                v.w += __ldg(&bias[n0 + c4 + 3]);
                uint2 hp, lp;
                split2(v.x, v.y, hp.x, lp.x);
                split2(v.z, v.w, hp.y, lp.y);
                size_t off = (size_t)(blockIdx.x * MT + r) * ldc + n0 + c4;
                *(uint2*)&Ch[off] = hp;
                *(uint2*)&Cl[off] = lp;
            }
        } else {
            float* crow = C + (size_t)blockIdx.x * MT * ldc + n0;
            #pragma unroll
            for (int q = 0; q < 8; ++q) {
                int f = tid + q * 256;
                int r = f >> 4, c4 = (f & 15) * 4;
                float4 v = *(float4*)&sC[r * CSTR + c4];
                v.x += __ldg(&bias[n0 + c4 + 0]);
                v.y += __ldg(&bias[n0 + c4 + 1]);
                v.z += __ldg(&bias[n0 + c4 + 2]);
                v.w += __ldg(&bias[n0 + c4 + 3]);
                *(float4*)&crow[(size_t)r * ldc + c4] = v;
            }
        }
    }
}

// -------- FA-style attention: CTA per window, 6-head loop, cp.async pipelined --------
// Tiles (bf16, 64x32, row stride 40): order Qh,Ql,Kh,Kl,Vh,Vl. V used via ldmatrix.trans.
#define TBUF 5120
#define HBUF (6 * TBUF)            // 30720
#define OFB0 0
#define OFB1 HBUF
#define OFRP (2 * HBUF)            // 61440
#define ATT_SMEM (OFRP + 6 * 228 * 4)   // 66912

__global__ __launch_bounds__(128, 3)
void attn_mma(const float* __restrict__ mask,
              const float* __restrict__ rpbt)
{
    extern __shared__ char smem[];
    const uint32_t sb = smem_u32(smem);
    float* srp = (float*)(smem + OFRP);

    const int tid  = threadIdx.x;
    const int wid  = tid >> 5;
    const int lane = tid & 31;
    const int win  = blockIdx.x;
    const float LOG2E = 1.4426950408889634f;

    // ---- rpbt all heads -> smem ([head][228]) ----
    for (int f = tid; f < 225 * NH; f += 128)
        srp[(f % NH) * 228 + f / NH] = __ldg(&rpbt[f]);

    // fragment index helpers
    const int asub = lane >> 3, ar = lane & 7;
    const uint32_t aqoff =
        (uint32_t)((wid * 16 + ar + (asub & 1) * 8) * 40 + (asub >> 1) * 8) * 2u;
    const uint32_t koff =
        (uint32_t)((ar + (asub >> 1) * 8) * 40 + (asub & 1) * 8) * 2u;
    const uint32_t voff =
        (uint32_t)((lane & 15) * 40 + (lane >> 4) * 8) * 2u;

    const int g  = wid * 16 + (lane >> 2);
    const int n2 = (lane & 3) * 2;
    const int r1 = g + 8;
    const int rh0 = g >> 3, rw0 = g & 7, rh1 = r1 >> 3, rw1 = r1 & 7;

    // ---- mask values for this thread's fragment slots (head-invariant) ----
    float mr[2][8][2];
    {
        const float* mg = mask + (size_t)(win & 63) * (NTOK * NTOK);
        #pragma unroll
        for (int jb = 0; jb < 8; ++jb) {
            float2 a = __ldg((const float2*)&mg[g  * 64 + jb * 8 + n2]);
            float2 b = __ldg((const float2*)&mg[r1 * 64 + jb * 8 + n2]);
            mr[0][jb][0] = a.x; mr[0][jb][1] = a.y;
            mr[1][jb][0] = b.x; mr[1][jb][1] = b.y;
        }
    }

    // ---- cp.async staging of one head's 6 tiles ----
    auto stage = [&](int head, uint32_t bufoff) {
        #pragma unroll
        for (int t = 0; t < 12; ++t) {
            int idx  = tid + t * 128;          // 1536 granules
            int tile = idx >> 8;
            int wi   = idx & 255;
            int r    = wi >> 2, gg = wi & 3;
            const __nv_bfloat16* src = (tile & 1) ? g_ql : g_qh;
            int col = (tile >> 1) * 192 + head * HD + gg * 8;
            cp16(sb + bufoff + (uint32_t)(tile * TBUF) + (uint32_t)(r * 40 + gg * 8) * 2u,
                 src + ((size_t)win * NTOK + r) * QKVN + col);
        }
        CP_COMMIT();
    };

    stage(0, OFB0);

    #pragma unroll 1
    for (int head = 0; head < NH; ++head) {
        CP_WAIT0();
        __syncthreads();   // tiles of this head ready; prior head's reads done

        if (head + 1 < NH)
            stage(head + 1, ((head + 1) & 1) ? OFB1 : OFB0);

        const uint32_t buf = sb + ((head & 1) ? OFB1 : OFB0);

        // ---- S = Q @ K^T (3-pass split), 16x64 per warp ----
        float s[4][2][4];
        #pragma unroll
        for (int j = 0; j < 4; ++j)
            #pragma unroll
            for (int h = 0; h < 2; ++h)
                #pragma unroll
                for (int e = 0; e < 4; ++e) s[j][h][e] = 0.f;

        #pragma unroll
        for (int pass = 0; pass < 3; ++pass) {
            uint32_t ab = buf + (pass == 2 ? TBUF : 0u);            // Ql : Qh
            uint32_t bb = buf + 2 * TBUF + (pass == 1 ? TBUF : 0u); // Kl : Kh
            #pragma unroll
            for (int ks = 0; ks < 2; ++ks) {
                uint32_t aq[4];
                LDSM4(aq, ab + aqoff + ks * 32);
                #pragma unroll
                for (int j16 = 0; j16 < 4; ++j16) {
                    uint32_t bk[4];
                    LDSM4(bk, bb + koff + j16 * 1280 + ks * 32);
                    MMA16816(s[j16][0], aq, bk[0], bk[1]);
                    MMA16816(s[j16][1], aq, bk[2], bk[3]);
                }
            }
        }

        // ---- rel-pos bias (smem) + mask (regs) ----
        const float* rp = srp + head * 228;
        #pragma unroll
        for (int j16 = 0; j16 < 4; ++j16)
            #pragma unroll
            for (int h = 0; h < 2; ++h) {
                int jb = j16 * 2 + h;
                #pragma unroll
                for (int e = 0; e < 2; ++e) {
                    int col = jb * 8 + n2 + e;
                    int ch = col >> 3, cw = col & 7;
                    s[j16][h][e]     += rp[(rh0 - ch + 7) * 15 + (rw0 - cw + 7)]
                                      + mr[0][jb][e];
                    s[j16][h][2 + e] += rp[(rh1 - ch + 7) * 15 + (rw1 - cw + 7)]
                                      + mr[1][jb][e];
                }
            }

        // ---- softmax (quad-shfl reduce) ----
        float m0 = -1e30f, m1 = -1e30f;
        #pragma unroll
        for (int j16 = 0; j16 < 4; ++j16)
            #pragma unroll
            for (int h = 0; h < 2; ++h) {
                m0 = fmaxf(m0, fmaxf(s[j16][h][0], s[j16][h][1]));
                m1 = fmaxf(m1, fmaxf(s[j16][h][2], s[j16][h][3]));
            }
        m0 = fmaxf(m0, __shfl_xor_sync(0xffffffffu, m0, 1));
        m0 = fmaxf(m0, __shfl_xor_sync(0xffffffffu, m0, 2));
        m1 = fmaxf(m1, __shfl_xor_sync(0xffffffffu, m1, 1));
        m1 = fmaxf(m1, __shfl_xor_sync(0xffffffffu, m1, 2));

        float t0 = 0.f, t1 = 0.f;
        #pragma unroll
        for (int j16 = 0; j16 < 4; ++j16)
            #pragma unroll
            for (int h = 0; h < 2; ++h) {
                s[j16][h][0] = ex2((s[j16][h][0] - m0) * LOG2E);
                s[j16][h][1] = ex2((s[j16][h][1] - m0) * LOG2E);
                s[j16][h][2] = ex2((s[j16][h][2] - m1) * LOG2E);
                s[j16][h][3] = ex2((s[j16][h][3] - m1) * LOG2E);
                t0 += s[j16][h][0] + s[j16][h][1];
                t1 += s[j16][h][2] + s[j16][h][3];
            }
        t0 += __shfl_xor_sync(0xffffffffu, t0, 1);
        t0 += __shfl_xor_sync(0xffffffffu, t0, 2);
        t1 += __shfl_xor_sync(0xffffffffu, t1, 1);
        t1 += __shfl_xor_sync(0xffffffffu, t1, 2);
        const float inv0 = 1.f / t0, inv1 = 1.f / t1;

        // ---- pack P (1/sum folded) to bf16 hi/lo A-frags ----
        uint32_t ph[4][4], pl[4][4];
        #pragma unroll
        for (int j16 = 0; j16 < 4; ++j16) {
            split2(s[j16][0][0] * inv0, s[j16][0][1] * inv0, ph[j16][0], pl[j16][0]);
            split2(s[j16][0][2] * inv1, s[j16][0][3] * inv1, ph[j16][1], pl[j16][1]);
            split2(s[j16][1][0] * inv0, s[j16][1][1] * inv0, ph[j16][2], pl[j16][2]);
            split2(s[j16][1][2] * inv1, s[j16][1][3] * inv1, ph[j16][3], pl[j16][3]);
        }

        // ---- O = P @ V (3-pass split), V row-major via ldmatrix.trans ----
        float o[4][4];
        #pragma unroll
        for (int n8 = 0; n8 < 4; ++n8)
            #pragma unroll
            for (int e = 0; e < 4; ++e) o[n8][e] = 0.f;

        #pragma unroll
        for (int pass = 0; pass < 3; ++pass) {
            uint32_t bvb = buf + 4 * TBUF + (pass == 1 ? TBUF : 0u); // Vl : Vh
            #pragma unroll
            for (int ks = 0; ks < 4; ++ks) {
                const uint32_t* ap = (pass == 2) ? pl[ks] : ph[ks];
                #pragma unroll
                for (int n16 = 0; n16 < 2; ++n16) {
                    uint32_t bv[4];
                    LDSM4T(bv, bvb + voff + (uint32_t)(ks * 1280 + n16 * 32));
                    MMA16816(o[n16 * 2 + 0], ap, bv[0], bv[1]);
                    MMA16816(o[n16 * 2 + 1], ap, bv[2], bv[3]);
                }
            }
        }

        // ---- write O fragments ----
        float* og = g_att + ((size_t)win * NTOK) * DIM + head * HD;
        #pragma unroll
        for (int n8 = 0; n8 < 4; ++n8) {
            int col = n8 * 8 + n2;
            *(float2*)&og[(size_t)g  * DIM + col] = make_float2(o[n8][0], o[n8][1]);
            *(float2*)&og[(size_t)r1 * DIM + col] = make_float2(o[n8][2], o[n8][3]);
        }
        __syncthreads();   // all smem reads of this buffer done before re-stage
    }
}

// ------------------------- launch -------------------------
extern "C" void kernel_launch(void* const* d_in, const int* in_sizes, int n_in,
                              void* d_out, int out_size)
{
    const float* x      = (const float*)d_in[0];
    const float* mask   = (const float*)d_in[1];
    const float* w_qkv  = (const float*)d_in[2];
    const float* b_qkv  = (const float*)d_in[3];
    const float* rpbt   = (const float*)d_in[4];
    const float* w_proj = (const float*)d_in[5];
    const float* b_proj = (const float*)d_in[6];
    float* out = (float*)d_out;

    void *p_qh, *p_ql, *p_att, *p_wqh, *p_wql, *p_wph, *p_wpl, *p_bq;
    cudaGetSymbolAddress(&p_qh,  g_qh);
    cudaGetSymbolAddress(&p_ql,  g_ql);
    cudaGetSymbolAddress(&p_att, g_att);
    cudaGetSymbolAddress(&p_wqh, g_wqh);
    cudaGetSymbolAddress(&p_wql, g_wql);
    cudaGetSymbolAddress(&p_wph, g_wph);
    cudaGetSymbolAddress(&p_wpl, g_wpl);
    cudaGetSymbolAddress(&p_bq,  g_bq);

    cudaFuncSetAttribute(gemm_mma,
                         cudaFuncAttributeMaxDynamicSharedMemorySize, GSMEM);
    cudaFuncSetAttribute(attn_mma,
                         cudaFuncAttributeMaxDynamicSharedMemorySize, ATT_SMEM);

    prep_kernel<<<432, 256>>>(w_qkv, b_qkv, w_proj);

    gemm_mma<<<MTOT / MT, 256, GSMEM>>>(
        x, (const __nv_bfloat16*)p_wqh, (const __nv_bfloat16*)p_wql,
        (const float*)p_bq, nullptr,
        (__nv_bfloat16*)p_qh, (__nv_bfloat16*)p_ql, QKVN, QKVN);

    attn_mma<<<NWIN, 128, ATT_SMEM>>>(mask, rpbt);

    gemm_mma<<<MTOT / MT, 256, GSMEM>>>(
        (const float*)p_att, (const __nv_bfloat16*)p_wph, (const __nv_bfloat16*)p_wpl,
        b_proj, out, nullptr, nullptr, DIM, DIM);
}